// round 5
// baseline (speedup 1.0000x reference)
#include <cuda_runtime.h>
#include <cstdint>
#include <math.h>

#define T_STEPS 512
#define BATCH   64
#define IN0     256
#define HID     512
#define NBLK    128
#define NTHR    128
#define JPB     4     // hidden units per block -> 16 gate rows

// -------- static device scratch --------
__device__ float g_hs[(size_t)T_STEPS * HID * BATCH];   // layer0 outputs [t][k][b]
__device__ float g_xT[(size_t)T_STEPS * IN0 * BATCH];   // inputs transposed [t][k][b]
__device__ float g_hT[2 * HID * BATCH];                 // double-buffered h, [k][b]
__device__ unsigned g_prod[16];
__device__ unsigned g_cons[16];
__device__ unsigned g_fb;        // full-barrier counter (monotone forever)
__device__ unsigned g_fb_base;   // snapshot at end of previous launch

// -------- packed f32x2 helpers --------
__device__ __forceinline__ unsigned long long dupf(float v) {
    unsigned long long r;
    asm("mov.b64 %0, {%1, %1};" : "=l"(r) : "f"(v));
    return r;
}
__device__ __forceinline__ void fma2(unsigned long long &d, unsigned long long a, unsigned long long b) {
    asm("fma.rn.f32x2 %0, %1, %2, %0;" : "+l"(d) : "l"(a), "l"(b));
}
__device__ __forceinline__ float sigf(float x) { return 1.0f / (1.0f + __expf(-x)); }

// -------- sync primitives --------
__device__ __forceinline__ void arrive(unsigned* ctr) {
    asm volatile("red.release.gpu.global.add.u32 [%0], 1;" :: "l"(ctr) : "memory");
}
__device__ __forceinline__ void wait_ge(const unsigned* ctr, unsigned target) {
    unsigned v;
    do {
        asm volatile("ld.acquire.gpu.global.u32 %0, [%1];" : "=r"(v) : "l"(ctr) : "memory");
    } while ((int)(v - target) < 0);
}
__device__ __forceinline__ void full_barrier(unsigned &expect) {
    __syncthreads();
    if (threadIdx.x == 0) {
        arrive(&g_fb);
        expect += NBLK;
        wait_ge(&g_fb, expect);
    }
    __syncthreads();
}

// -------- cp.async --------
__device__ __forceinline__ void cp16(uint32_t sm, const float* g) {
    asm volatile("cp.async.cg.shared.global [%0], [%1], 16;" :: "r"(sm), "l"(g));
}
__device__ __forceinline__ void cp_commit() { asm volatile("cp.async.commit_group;" ::: "memory"); }
template<int N>
__device__ __forceinline__ void cp_wait() { asm volatile("cp.async.wait_group %0;" :: "n"(N) : "memory"); }

// one chunk = 128k x 64b floats = 32KB; 16 float4 per thread (128 threads)
__device__ __forceinline__ void issue_chunk(float* smdst, const float* src, int tid) {
    uint32_t s = (uint32_t)__cvta_generic_to_shared(smdst);
#pragma unroll
    for (int q = 0; q < 16; ++q) {
        int i4 = tid + q * NTHR;
        cp16(s + i4 * 16, src + i4 * 4);
    }
    cp_commit();
}

// smem layout (floats)
//  w_s   [1024][16]     = 16384
//  hbuf  3 x [128][64]  = 24576
//  red   [128 rows][66] =  8448   (row = kc*16 + r; padded pitch 66 floats = 33 u64)
//  bias  [16]
#define OFF_W    0
#define OFF_HBUF 16384
#define OFF_RED  (16384 + 24576)
#define OFF_BIAS (OFF_RED + 8448)
#define SMEM_FLOATS (OFF_BIAS + 16)

// -------- inner chunk compute: 16 kk, tile 8 rows x 8 batch --------
__device__ __forceinline__ void compute_chunk(const float* hb, const float* wp,
                                              unsigned long long acc[32])
{
    ulonglong2 h0 = *(const ulonglong2*)(hb);
    ulonglong2 h1 = *(const ulonglong2*)(hb + 4);
    float4 w0 = *(const float4*)(wp);
    float4 w1 = *(const float4*)(wp + 4);
#pragma unroll 4
    for (int kk = 0; kk < 16; ++kk) {
        // prefetch kk+1 (one-past-end read stays inside dynamic smem; value unused)
        ulonglong2 nh0 = *(const ulonglong2*)(hb + (kk + 1) * 64);
        ulonglong2 nh1 = *(const ulonglong2*)(hb + (kk + 1) * 64 + 4);
        float4     nw0 = *(const float4*)(wp + (kk + 1) * 16);
        float4     nw1 = *(const float4*)(wp + (kk + 1) * 16 + 4);

        unsigned long long wd0 = dupf(w0.x), wd1 = dupf(w0.y), wd2 = dupf(w0.z), wd3 = dupf(w0.w);
        unsigned long long wd4 = dupf(w1.x), wd5 = dupf(w1.y), wd6 = dupf(w1.z), wd7 = dupf(w1.w);
        unsigned long long hv0 = h0.x, hv1 = h0.y, hv2 = h1.x, hv3 = h1.y;

        fma2(acc[ 0], hv0, wd0); fma2(acc[ 1], hv1, wd0); fma2(acc[ 2], hv2, wd0); fma2(acc[ 3], hv3, wd0);
        fma2(acc[ 4], hv0, wd1); fma2(acc[ 5], hv1, wd1); fma2(acc[ 6], hv2, wd1); fma2(acc[ 7], hv3, wd1);
        fma2(acc[ 8], hv0, wd2); fma2(acc[ 9], hv1, wd2); fma2(acc[10], hv2, wd2); fma2(acc[11], hv3, wd2);
        fma2(acc[12], hv0, wd3); fma2(acc[13], hv1, wd3); fma2(acc[14], hv2, wd3); fma2(acc[15], hv3, wd3);
        fma2(acc[16], hv0, wd4); fma2(acc[17], hv1, wd4); fma2(acc[18], hv2, wd4); fma2(acc[19], hv3, wd4);
        fma2(acc[20], hv0, wd5); fma2(acc[21], hv1, wd5); fma2(acc[22], hv2, wd5); fma2(acc[23], hv3, wd5);
        fma2(acc[24], hv0, wd6); fma2(acc[25], hv1, wd6); fma2(acc[26], hv2, wd6); fma2(acc[27], hv3, wd6);
        fma2(acc[28], hv0, wd7); fma2(acc[29], hv1, wd7); fma2(acc[30], hv2, wd7); fma2(acc[31], hv3, wd7);

        h0 = nh0; h1 = nh1; w0 = nw0; w1 = nw1;
    }
}

template<int K_IN>
__device__ void run_layer(int layer, const float* __restrict__ xT,
                          const float* __restrict__ h0l, const float* __restrict__ c0l,
                          const float* __restrict__ w_ih, const float* __restrict__ w_hh,
                          const float* __restrict__ b_ih, const float* __restrict__ b_hh,
                          float* __restrict__ out, float* smem, unsigned &fb_expect)
{
    constexpr int XC = K_IN / 128;
    constexpr int K_TOT = K_IN + HID;

    float* w_s    = smem + OFF_W;
    float* hbuf   = smem + OFF_HBUF;
    float* red_f  = smem + OFF_RED;
    unsigned long long* red_u = (unsigned long long*)red_f;
    float* bias_s = smem + OFF_BIAS;

    const int tid = threadIdx.x;
    const int j0  = blockIdx.x * JPB;

    // compute roles: kc 0..7 (split-K in chunk), bb 0..7 (8 batches), rg 0..1 (8 rows)
    const int kc = tid >> 4;
    const int rg = (tid >> 3) & 1;
    const int bb = tid & 7;

    // ---- init ----
    full_barrier(fb_expect);
    if (tid < 16) { g_prod[tid] = 0; g_cons[tid] = 0; }

#pragma unroll 1
    for (int rr = 0; rr < 16; ++rr) {
        int row = (rr >> 2) * HID + j0 + (rr & 3);
        for (int kg = tid; kg < K_TOT; kg += NTHR) {
            float v = (kg < K_IN) ? w_ih[row * K_IN + kg]
                                  : w_hh[row * HID + (kg - K_IN)];
            w_s[kg * 16 + rr] = v;
        }
    }
    if (tid < 16) {
        int row = (tid >> 2) * HID + j0 + (tid & 3);
        bias_s[tid] = b_ih[row] + b_hh[row];
    }
    float c_reg0, c_reg1;
    {
        int i0g = tid,         i1g = tid + 128;
        int jjA = i0g >> 6, bA = i0g & 63;
        int jjB = i1g >> 6, bB = i1g & 63;
        c_reg0 = c0l[bA * HID + j0 + jjA];
        c_reg1 = c0l[bB * HID + j0 + jjB];
        g_hT[(j0 + jjA) * BATCH + bA] = h0l[bA * HID + j0 + jjA];
        g_hT[(j0 + jjB) * BATCH + bB] = h0l[bB * HID + j0 + jjB];
    }
    full_barrier(fb_expect);

    // prefetch step-0 x chunks
    issue_chunk(hbuf + 0 * 8192, xT + 0, tid);
    issue_chunk(hbuf + 1 * 8192, xT + (size_t)128 * BATCH, tid);

    for (int t = 0; t < T_STEPS; ++t) {
        const float* xt   = xT + (size_t)t * K_IN * BATCH;
        const float* hcur = g_hT + (t & 1) * HID * BATCH;

        unsigned long long acc[32];
#pragma unroll
        for (int j = 0; j < 32; ++j) acc[j] = 0ull;

        const int hb_off = kc * 16 * 64 + bb * 8;
        const int wp_off = kc * 16 * 16 + rg * 8;

        // ---- X phase ----
#pragma unroll
        for (int c = 0; c < XC; ++c) {
            if (c + 2 < XC) {
                issue_chunk(hbuf + ((c + 2) % 3) * 8192, xt + (size_t)(c + 2) * 128 * BATCH, tid);
                cp_wait<2>();
            } else if (c + 1 < XC) cp_wait<1>();
            else                   cp_wait<0>();
            __syncthreads();
            compute_chunk(hbuf + (c % 3) * 8192 + hb_off, w_s + c * 128 * 16 + wp_off, acc);
            __syncthreads();
        }

        // ---- wait: all blocks produced h_t ----
        if (t > 0) {
            if (tid == 0) {
                unsigned target = 128u * ((unsigned)(t >> 4) + 1u) - (((t & 15) == 0) ? 128u : 0u);
                wait_ge(&g_prod[t & 15], target);
            }
            __syncthreads();
        }

        // ---- H phase (4 chunks) ----
        issue_chunk(hbuf + ((XC + 0) % 3) * 8192, hcur + (size_t)0 * 128 * BATCH, tid);
        issue_chunk(hbuf + ((XC + 1) % 3) * 8192, hcur + (size_t)128 * BATCH, tid);
#pragma unroll
        for (int i = 0; i < 4; ++i) {
            if (i + 2 < 4) {
                issue_chunk(hbuf + ((XC + i + 2) % 3) * 8192, hcur + (size_t)(i + 2) * 128 * BATCH, tid);
                cp_wait<2>();
            } else if (i + 1 < 4) cp_wait<1>();
            else                  cp_wait<0>();
            __syncthreads();
            compute_chunk(hbuf + ((XC + i) % 3) * 8192 + hb_off,
                          w_s + (XC + i) * 128 * 16 + wp_off, acc);
            __syncthreads();
        }
        if (tid == 0) arrive(&g_cons[t & 15]);

        // ---- reduction: store packed u64 partials ----
        // row = kc*16 + rg*8 + r ; u64 col = bb*4 + bp
#pragma unroll
        for (int r = 0; r < 8; ++r) {
#pragma unroll
            for (int bp = 0; bp < 4; ++bp)
                red_u[(kc * 16 + rg * 8 + r) * 33 + bb * 4 + bp] = acc[r * 4 + bp];
        }
        __syncthreads();

        // ---- gates: 2 (b,j) pairs per thread ----
        float hnA, hnB, cnA, cnB;
        int jA, bA, jB, bB;
        {
            int iA = tid, iB = tid + 128;
            int jjA = iA >> 6; bA = iA & 63; jA = j0 + jjA;
            int jjB = iB >> 6; bB = iB & 63; jB = j0 + jjB;
#pragma unroll
            for (int p = 0; p < 2; ++p) {
                int jj = p ? jjB : jjA;
                int b  = p ? bB  : bA;
                float s0 = bias_s[jj], s1 = bias_s[4 + jj], s2 = bias_s[8 + jj], s3 = bias_s[12 + jj];
#pragma unroll
                for (int k8 = 0; k8 < 8; ++k8) {
                    s0 += red_f[(k8 * 16 +      jj) * 66 + b];
                    s1 += red_f[(k8 * 16 +  4 + jj) * 66 + b];
                    s2 += red_f[(k8 * 16 +  8 + jj) * 66 + b];
                    s3 += red_f[(k8 * 16 + 12 + jj) * 66 + b];
                }
                float ci = p ? c_reg1 : c_reg0;
                float cn = sigf(s1) * ci + sigf(s0) * tanhf(s2);
                float hn = sigf(s3) * tanhf(cn);
                if (p) { c_reg1 = cn; hnB = hn; cnB = cn; }
                else   { c_reg0 = cn; hnA = hn; cnA = cn; }
            }
        }

        // prefetch next step's x chunks
        if (t + 1 < T_STEPS) {
            const float* xn = xT + (size_t)(t + 1) * K_IN * BATCH;
            issue_chunk(hbuf + 0 * 8192, xn, tid);
            issue_chunk(hbuf + 1 * 8192, xn + (size_t)128 * BATCH, tid);
        }

        // ---- wait: everyone consumed h_{t-1} before overwriting its buffer ----
        if (t >= 1) {
            if (tid == 0) {
                unsigned target = 128u * ((unsigned)((t - 1) >> 4) + 1u);
                wait_ge(&g_cons[(t - 1) & 15], target);
            }
            __syncthreads();
        }

        // ---- write h_{t+1} ----
        {
            float* hdst = g_hT + ((t + 1) & 1) * HID * BATCH;
            hdst[jA * BATCH + bA] = hnA;
            hdst[jB * BATCH + bB] = hnB;
            if (layer == 0) {
                g_hs[((size_t)t * HID + jA) * BATCH + bA] = hnA;
                g_hs[((size_t)t * HID + jB) * BATCH + bB] = hnB;
            }
            if (t == T_STEPS - 1) {
                out[layer * BATCH * HID + bA * HID + jA] = hnA;
                out[layer * BATCH * HID + bB * HID + jB] = hnB;
                out[2 * BATCH * HID + layer * BATCH * HID + bA * HID + jA] = cnA;
                out[2 * BATCH * HID + layer * BATCH * HID + bB * HID + jB] = cnB;
            }
        }
        __syncthreads();
        if (tid == 0) arrive(&g_prod[(t + 1) & 15]);
    }

    full_barrier(fb_expect);
}

__global__ void __launch_bounds__(NTHR, 1)
lstm_scan_kernel(const float* __restrict__ h0,
                 const float* __restrict__ c0,
                 const float* __restrict__ w_ih0, const float* __restrict__ w_hh0,
                 const float* __restrict__ b_ih0, const float* __restrict__ b_hh0,
                 const float* __restrict__ w_ih1, const float* __restrict__ w_hh1,
                 const float* __restrict__ b_ih1, const float* __restrict__ b_hh1,
                 float* __restrict__ out)
{
    extern __shared__ float smem[];
    unsigned fb_expect = g_fb_base;

    run_layer<IN0>(0, g_xT, h0, c0, w_ih0, w_hh0, b_ih0, b_hh0, out, smem, fb_expect);
    run_layer<HID>(1, g_hs, h0 + BATCH * HID, c0 + BATCH * HID,
                   w_ih1, w_hh1, b_ih1, b_hh1, out, smem, fb_expect);

    if (blockIdx.x == 0 && threadIdx.x == 0)
        g_fb_base = fb_expect;
}

// -------- prepass: transpose inputs to g_xT AND copy passthrough to out tail --------
__global__ void prep_kernel(const float* __restrict__ in, float* __restrict__ out_tail)
{
    __shared__ float tile[32][33];
    int t  = blockIdx.x;
    int i0 = blockIdx.y * 32;
    int b0 = blockIdx.z * 32;
    int tx = threadIdx.x, ty = threadIdx.y;   // 32 x 8
    const float* ip = in + (size_t)t * BATCH * IN0;
    float* cp = out_tail + (size_t)t * BATCH * IN0;
    float* op = g_xT + (size_t)t * IN0 * BATCH;
#pragma unroll
    for (int yy = 0; yy < 32; yy += 8) {
        float v = ip[(b0 + ty + yy) * IN0 + i0 + tx];
        tile[ty + yy][tx] = v;
        cp[(b0 + ty + yy) * IN0 + i0 + tx] = v;
    }
    __syncthreads();
#pragma unroll
    for (int yy = 0; yy < 32; yy += 8)
        op[(i0 + ty + yy) * BATCH + b0 + tx] = tile[tx][ty + yy];
}

extern "C" void kernel_launch(void* const* d_in, const int* in_sizes, int n_in,
                              void* d_out, int out_size)
{
    const float* inputs = (const float*)d_in[0];
    const float* h0     = (const float*)d_in[1];
    const float* c0     = (const float*)d_in[2];
    const float* w_ih0  = (const float*)d_in[3];
    const float* w_hh0  = (const float*)d_in[4];
    const float* b_ih0  = (const float*)d_in[5];
    const float* b_hh0  = (const float*)d_in[6];
    const float* w_ih1  = (const float*)d_in[7];
    const float* w_hh1  = (const float*)d_in[8];
    const float* b_ih1  = (const float*)d_in[9];
    const float* b_hh1  = (const float*)d_in[10];
    float* out = (float*)d_out;

    (void)in_sizes; (void)n_in; (void)out_size;

    cudaFuncSetAttribute(lstm_scan_kernel,
                         cudaFuncAttributeMaxDynamicSharedMemorySize,
                         SMEM_FLOATS * (int)sizeof(float));

    prep_kernel<<<dim3(T_STEPS, IN0 / 32, BATCH / 32), dim3(32, 8)>>>(
        inputs, out + 4 * BATCH * HID);

    lstm_scan_kernel<<<NBLK, NTHR, SMEM_FLOATS * sizeof(float)>>>(
        h0, c0,
        w_ih0, w_hh0, b_ih0, b_hh0,
        w_ih1, w_hh1, b_ih1, b_hh1,
        out);
}

// round 6
// speedup vs baseline: 1.2059x; 1.2059x over previous
#include <cuda_runtime.h>
#include <cstdint>
#include <math.h>

#define T_STEPS 512
#define BATCH   64
#define IN0     256
#define HID     512
#define NBLK    128
#define NTHR    256
#define ROWS    32      // gate rows per block (8 hidden units x 4 gates)
#define BHALF   32      // batch per block

// -------- static device scratch --------
__device__ float g_hs[(size_t)T_STEPS * HID * BATCH];   // layer0 outputs [t][k][64]
__device__ float g_xT[(size_t)T_STEPS * IN0 * BATCH];   // inputs transposed [t][k][64]
__device__ float g_hT[2 * HID * BATCH];                 // double-buffered h [buf][k][64]
__device__ unsigned g_prod[32];    // [bg][slot16]
__device__ unsigned g_cons[32];
__device__ unsigned g_fb;
__device__ unsigned g_fb_base;

// -------- packed f32x2 helpers --------
__device__ __forceinline__ unsigned long long dupf(float v) {
    unsigned long long r;
    asm("mov.b64 %0, {%1, %1};" : "=l"(r) : "f"(v));
    return r;
}
__device__ __forceinline__ void fma2(unsigned long long &d, unsigned long long a, unsigned long long b) {
    asm("fma.rn.f32x2 %0, %1, %2, %0;" : "+l"(d) : "l"(a), "l"(b));
}
__device__ __forceinline__ float sigf(float x) { return 1.0f / (1.0f + __expf(-x)); }

// -------- sync primitives --------
__device__ __forceinline__ void arrive(unsigned* ctr) {
    asm volatile("red.release.gpu.global.add.u32 [%0], 1;" :: "l"(ctr) : "memory");
}
__device__ __forceinline__ void wait_ge(const unsigned* ctr, unsigned target) {
    unsigned v;
    do {
        asm volatile("ld.acquire.gpu.global.u32 %0, [%1];" : "=r"(v) : "l"(ctr) : "memory");
    } while ((int)(v - target) < 0);
}
__device__ __forceinline__ void full_barrier(unsigned &expect) {
    __syncthreads();
    if (threadIdx.x == 0) {
        arrive(&g_fb);
        expect += NBLK;
        wait_ge(&g_fb, expect);
    }
    __syncthreads();
}

// -------- cp.async --------
__device__ __forceinline__ void cp16(uint32_t sm, const float* g) {
    asm volatile("cp.async.cg.shared.global [%0], [%1], 16;" :: "r"(sm), "l"(g));
}
__device__ __forceinline__ void cp_commit() { asm volatile("cp.async.commit_group;" ::: "memory"); }
template<int N>
__device__ __forceinline__ void cp_wait() { asm volatile("cp.async.wait_group %0;" :: "n"(N) : "memory"); }

// one chunk = 128 k x 32 b = 16KB. src has row stride 64 floats (full batch),
// we copy a 32-float column window. 4 cp16 per thread.
__device__ __forceinline__ void issue_chunk(float* smdst, const float* src, int tid) {
    uint32_t s = (uint32_t)__cvta_generic_to_shared(smdst);
#pragma unroll
    for (int q = 0; q < 4; ++q) {
        int i4 = tid + q * NTHR;          // 0..1023
        int k   = i4 >> 3;                // 0..127
        int off = i4 & 7;                 // 0..7 (16B units within 128B row)
        cp16(s + i4 * 16, src + k * 64 + off * 4);
    }
    cp_commit();
}

// smem layout (floats)
//  w_s   [1024][32]        = 32768   (layer0 uses first 768 rows)
//  hbuf  4 x [128][32]     = 16384
//  red   [8*16 u64rows][33 u64] = 4224 u64 = 8448 floats
//  bias  [32]
#define OFF_W    0
#define OFF_HBUF 32768
#define OFF_RED  (32768 + 16384)
#define OFF_BIAS (OFF_RED + 8448)
#define SMEM_FLOATS (OFF_BIAS + 32)

// -------- inner chunk compute: 16 kk, tile 4 row-pairs x 4 batch --------
// hb = slot + bp*4 ; wp = w_s + (chunk*128 + kc*16)*32 + rg*8
__device__ __forceinline__ void compute_chunk(const float* hb, const float* wp,
                                              unsigned long long acc[16])
{
    float4 h4 = *(const float4*)hb;
    ulonglong2 wA = *(const ulonglong2*)wp;
    ulonglong2 wB = *(const ulonglong2*)(wp + 4);
#pragma unroll
    for (int kk = 0; kk < 16; ++kk) {
        float4     h4n = *(const float4*)(hb + (kk + 1) * 32);
        ulonglong2 wAn = *(const ulonglong2*)(wp + (kk + 1) * 32);
        ulonglong2 wBn = *(const ulonglong2*)(wp + (kk + 1) * 32 + 4);

        unsigned long long hd0 = dupf(h4.x), hd1 = dupf(h4.y),
                           hd2 = dupf(h4.z), hd3 = dupf(h4.w);

        fma2(acc[ 0], wA.x, hd0); fma2(acc[ 1], wA.x, hd1); fma2(acc[ 2], wA.x, hd2); fma2(acc[ 3], wA.x, hd3);
        fma2(acc[ 4], wA.y, hd0); fma2(acc[ 5], wA.y, hd1); fma2(acc[ 6], wA.y, hd2); fma2(acc[ 7], wA.y, hd3);
        fma2(acc[ 8], wB.x, hd0); fma2(acc[ 9], wB.x, hd1); fma2(acc[10], wB.x, hd2); fma2(acc[11], wB.x, hd3);
        fma2(acc[12], wB.y, hd0); fma2(acc[13], wB.y, hd1); fma2(acc[14], wB.y, hd2); fma2(acc[15], wB.y, hd3);

        h4 = h4n; wA = wAn; wB = wBn;
    }
}

template<int K_IN>
__device__ void run_layer(int layer, const float* __restrict__ xT,
                          const float* __restrict__ h0l, const float* __restrict__ c0l,
                          const float* __restrict__ w_ih, const float* __restrict__ w_hh,
                          const float* __restrict__ b_ih, const float* __restrict__ b_hh,
                          float* __restrict__ out, float* smem, unsigned &fb_expect)
{
    constexpr int XC = K_IN / 128;           // x chunks (2 or 4)
    constexpr int NC = XC + 4;               // total chunks (6 or 8)
    constexpr int K_TOT = K_IN + HID;

    float* w_s   = smem + OFF_W;
    float* hbuf  = smem + OFF_HBUF;
    float* red_f = smem + OFF_RED;
    unsigned long long* red_u = (unsigned long long*)red_f;
    float* bias_s = smem + OFF_BIAS;

    const int tid = threadIdx.x;
    const int bg  = blockIdx.x & 1;          // batch half
    const int hg  = blockIdx.x >> 1;         // hidden group (8 units)

    // compute roles: warp = split-K group
    const int kc = tid >> 5;                 // 0..7
    const int rg = (tid >> 3) & 3;           // 0..3 (row-pair quads)
    const int bp = tid & 7;                  // 0..7 (4-batch groups)

    // epilogue roles: one cell each
    const int jj = tid >> 5;                 // 0..7 hidden unit in group
    const int bl = tid & 31;                 // local batch

    unsigned* prod = g_prod + bg * 16;
    unsigned* cons = g_cons + bg * 16;

    // ---- init ----
    full_barrier(fb_expect);
    if (tid < 32) { g_prod[tid] = 0; g_cons[tid] = 0; }

#pragma unroll 1
    for (int rr = 0; rr < ROWS; ++rr) {
        int row = (rr >> 3) * HID + hg * 8 + (rr & 7);    // gate*H + j
        for (int kg = tid; kg < K_TOT; kg += NTHR) {
            float v = (kg < K_IN) ? w_ih[row * K_IN + kg]
                                  : w_hh[row * HID + (kg - K_IN)];
            w_s[kg * 32 + rr] = v;
        }
    }
    if (tid < 32) {
        int row = (tid >> 3) * HID + hg * 8 + (tid & 7);
        bias_s[tid] = b_ih[row] + b_hh[row];
    }
    float c_reg;
    {
        int j = hg * 8 + jj, b = bg * 32 + bl;
        c_reg = c0l[b * HID + j];
        g_hT[j * 64 + b] = h0l[b * HID + j];      // buffer 0
    }
    full_barrier(fb_expect);

    // prefetch step-0 x chunks 0,1
    {
        const float* x0 = xT + bg * 32;
        issue_chunk(hbuf + 0 * 4096, x0, tid);
        issue_chunk(hbuf + 1 * 4096, x0 + (size_t)128 * 64, tid);
    }

    for (int t = 0; t < T_STEPS; ++t) {
        const float* xt   = xT + (size_t)t * K_IN * 64 + bg * 32;
        const float* hcur = g_hT + (t & 1) * HID * 64 + bg * 32;

        unsigned long long acc[16];
#pragma unroll
        for (int j = 0; j < 16; ++j) acc[j] = 0ull;

        const int hb_off = kc * 16 * 32 + bp * 4;

#pragma unroll 1
        for (int c = 0; c < NC; ++c) {
            if (c + 2 < NC) {
                if (c + 2 == XC && t > 0) {
                    // h_t must be published by all blocks of this half
                    if (tid == 0) {
                        unsigned rounds = (unsigned)(t >> 4) + 1u - (((t & 15) == 0) ? 1u : 0u);
                        wait_ge(&prod[t & 15], 64u * rounds);
                    }
                    __syncthreads();
                }
                const float* src = (c + 2 < XC) ? (xt + (size_t)(c + 2) * 128 * 64)
                                                : (hcur + (size_t)(c + 2 - XC) * 128 * 64);
                issue_chunk(hbuf + ((c + 2) & 3) * 4096, src, tid);
                cp_wait<2>();
            } else if (c + 1 < NC) cp_wait<1>();
            else                   cp_wait<0>();
            __syncthreads();
            compute_chunk(hbuf + (c & 3) * 4096 + hb_off,
                          w_s + (c * 128 + kc * 16) * 32 + rg * 8, acc);
        }
        // all h_t bytes landed in smem (last sync covered every thread's groups)
        if (tid == 0) arrive(&cons[t & 15]);

        // ---- reduction: store packed u64 partials ----
        // u64 row = kc*16 + rg*4 + rp  (row-pair), col = bp*4 + bi, pitch 33
#pragma unroll
        for (int rp = 0; rp < 4; ++rp) {
#pragma unroll
            for (int bi = 0; bi < 4; ++bi)
                red_u[(kc * 16 + rg * 4 + rp) * 33 + bp * 4 + bi] = acc[rp * 4 + bi];
        }
        __syncthreads();

        // ---- gates: 1 cell per thread ----
        float hn, cn;
        {
            float s0 = bias_s[jj], s1 = bias_s[8 + jj], s2 = bias_s[16 + jj], s3 = bias_s[24 + jj];
            const int lane = bl * 2 + (jj & 1);
            const int rphi = jj >> 1;
#pragma unroll
            for (int k8 = 0; k8 < 8; ++k8) {
                s0 += red_f[(k8 * 16 +      rphi) * 66 + lane];
                s1 += red_f[(k8 * 16 +  4 + rphi) * 66 + lane];
                s2 += red_f[(k8 * 16 +  8 + rphi) * 66 + lane];
                s3 += red_f[(k8 * 16 + 12 + rphi) * 66 + lane];
            }
            cn = sigf(s1) * c_reg + sigf(s0) * tanhf(s2);
            hn = sigf(s3) * tanhf(cn);
            c_reg = cn;
        }

        // prefetch next step's x chunks 0,1 (slots 0,1 safe: last computed at c=NC-4,NC-3)
        if (t + 1 < T_STEPS) {
            const float* xn = xT + (size_t)(t + 1) * K_IN * 64 + bg * 32;
            issue_chunk(hbuf + 0 * 4096, xn, tid);
            issue_chunk(hbuf + 1 * 4096, xn + (size_t)128 * 64, tid);
        }

        // ---- wait: this half consumed h_{t-1} before overwriting its buffer ----
        if (t >= 1) {
            if (tid == 0) {
                unsigned rounds = (unsigned)((t - 1) >> 4) + 1u;
                wait_ge(&cons[(t - 1) & 15], 64u * rounds);
            }
            __syncthreads();
        }

        // ---- write h_{t+1} ----
        {
            int j = hg * 8 + jj, b = bg * 32 + bl;
            g_hT[((t + 1) & 1) * HID * 64 + j * 64 + b] = hn;
            if (layer == 0)
                g_hs[((size_t)t * HID + j) * 64 + b] = hn;
            if (t == T_STEPS - 1) {
                out[layer * BATCH * HID + b * HID + j] = hn;
                out[2 * BATCH * HID + layer * BATCH * HID + b * HID + j] = cn;
            }
        }
        __syncthreads();
        if (tid == 0) arrive(&prod[(t + 1) & 15]);
    }

    full_barrier(fb_expect);
}

__global__ void __launch_bounds__(NTHR, 1)
lstm_scan_kernel(const float* __restrict__ h0,
                 const float* __restrict__ c0,
                 const float* __restrict__ w_ih0, const float* __restrict__ w_hh0,
                 const float* __restrict__ b_ih0, const float* __restrict__ b_hh0,
                 const float* __restrict__ w_ih1, const float* __restrict__ w_hh1,
                 const float* __restrict__ b_ih1, const float* __restrict__ b_hh1,
                 float* __restrict__ out)
{
    extern __shared__ float smem[];
    unsigned fb_expect = g_fb_base;

    run_layer<IN0>(0, g_xT, h0, c0, w_ih0, w_hh0, b_ih0, b_hh0, out, smem, fb_expect);
    run_layer<HID>(1, g_hs, h0 + BATCH * HID, c0 + BATCH * HID,
                   w_ih1, w_hh1, b_ih1, b_hh1, out, smem, fb_expect);

    if (blockIdx.x == 0 && threadIdx.x == 0)
        g_fb_base = fb_expect;
}

// -------- prepass: transpose inputs to g_xT AND copy passthrough to out tail --------
__global__ void prep_kernel(const float* __restrict__ in, float* __restrict__ out_tail)
{
    __shared__ float tile[32][33];
    int t  = blockIdx.x;
    int i0 = blockIdx.y * 32;
    int b0 = blockIdx.z * 32;
    int tx = threadIdx.x, ty = threadIdx.y;   // 32 x 8
    const float* ip = in + (size_t)t * BATCH * IN0;
    float* cp = out_tail + (size_t)t * BATCH * IN0;
    float* op = g_xT + (size_t)t * IN0 * BATCH;
#pragma unroll
    for (int yy = 0; yy < 32; yy += 8) {
        float v = ip[(b0 + ty + yy) * IN0 + i0 + tx];
        tile[ty + yy][tx] = v;
        cp[(b0 + ty + yy) * IN0 + i0 + tx] = v;
    }
    __syncthreads();
#pragma unroll
    for (int yy = 0; yy < 32; yy += 8)
        op[(i0 + ty + yy) * BATCH + b0 + tx] = tile[tx][ty + yy];
}

extern "C" void kernel_launch(void* const* d_in, const int* in_sizes, int n_in,
                              void* d_out, int out_size)
{
    const float* inputs = (const float*)d_in[0];
    const float* h0     = (const float*)d_in[1];
    const float* c0     = (const float*)d_in[2];
    const float* w_ih0  = (const float*)d_in[3];
    const float* w_hh0  = (const float*)d_in[4];
    const float* b_ih0  = (const float*)d_in[5];
    const float* b_hh0  = (const float*)d_in[6];
    const float* w_ih1  = (const float*)d_in[7];
    const float* w_hh1  = (const float*)d_in[8];
    const float* b_ih1  = (const float*)d_in[9];
    const float* b_hh1  = (const float*)d_in[10];
    float* out = (float*)d_out;

    (void)in_sizes; (void)n_in; (void)out_size;

    cudaFuncSetAttribute(lstm_scan_kernel,
                         cudaFuncAttributeMaxDynamicSharedMemorySize,
                         SMEM_FLOATS * (int)sizeof(float));

    prep_kernel<<<dim3(T_STEPS, IN0 / 32, BATCH / 32), dim3(32, 8)>>>(
        inputs, out + 4 * BATCH * HID);

    lstm_scan_kernel<<<NBLK, NTHR, SMEM_FLOATS * sizeof(float)>>>(
        h0, c0,
        w_ih0, w_hh0, b_ih0, b_hh0,
        w_ih1, w_hh1, b_ih1, b_hh1,
        out);
}